// round 8
// baseline (speedup 1.0000x reference)
#include <cuda_runtime.h>

#define DIM 64
#define MAX_SRC 100000

// Scratch for h_src = x_src @ W_nei^T  (25.6 MB, fits in L2 alongside out)
__device__ float g_h_src[(size_t)MAX_SRC * DIM];

// out[row] = x[row] @ W^T (+ bias). One thread per row, W^T staged in smem.
__global__ void linear64_kernel(const float* __restrict__ x,
                                const float* __restrict__ W,
                                const float* __restrict__ bias,
                                float* __restrict__ out, int n)
{
    __shared__ float Wt[DIM * DIM];  // Wt[k*64 + c] = W[c*64 + k]
    __shared__ float bs[DIM];
    int tid = threadIdx.x;
    for (int i = tid; i < DIM * DIM; i += blockDim.x) {
        int c = i >> 6, k = i & 63;
        Wt[k * DIM + c] = W[i];
    }
    if (tid < DIM) bs[tid] = bias ? bias[tid] : 0.0f;
    __syncthreads();

    int row = blockIdx.x * blockDim.x + tid;
    if (row >= n) return;

    const float4* xr = reinterpret_cast<const float4*>(x + (size_t)row * DIM);

    float acc[DIM];
    #pragma unroll
    for (int c = 0; c < DIM; c++) acc[c] = bs[c];

    #pragma unroll 2
    for (int k4 = 0; k4 < DIM / 4; k4++) {
        float4 xv = xr[k4];
        #pragma unroll
        for (int j = 0; j < 4; j++) {
            float xk = (j == 0) ? xv.x : (j == 1) ? xv.y : (j == 2) ? xv.z : xv.w;
            int k = k4 * 4 + j;
            const float4* wrow = reinterpret_cast<const float4*>(&Wt[k * DIM]);
            #pragma unroll
            for (int c4 = 0; c4 < DIM / 4; c4++) {
                float4 w = wrow[c4];  // broadcast across lanes -> conflict-free
                acc[c4 * 4 + 0] += xk * w.x;
                acc[c4 * 4 + 1] += xk * w.y;
                acc[c4 * 4 + 2] += xk * w.z;
                acc[c4 * 4 + 3] += xk * w.w;
            }
        }
    }

    float4* o = reinterpret_cast<float4*>(out + (size_t)row * DIM);
    #pragma unroll
    for (int c4 = 0; c4 < DIM / 4; c4++)
        o[c4] = make_float4(acc[c4 * 4 + 0], acc[c4 * 4 + 1],
                            acc[c4 * 4 + 2], acc[c4 * 4 + 3]);
}

// Per edge: out[dst] += h_src[src] * w.  16 threads per edge, float4 lanes,
// vectorized fp32 reduction (red.global.add.v4.f32, sm_90+).
// NOTE: edge indices are int32 (JAX x64 disabled downcasts the int64 request).
__global__ void scatter_kernel(const int* __restrict__ sidx,
                               const int* __restrict__ didx,
                               const float* __restrict__ ew,
                               float* __restrict__ out, int E)
{
    long long t = (long long)blockIdx.x * blockDim.x + threadIdx.x;
    int edge = (int)(t >> 4);
    int sub  = (int)(t & 15);
    if (edge >= E) return;

    int s = __ldg(&sidx[edge]);
    int d = __ldg(&didx[edge]);
    float w = __ldg(&ew[edge]);

    const float4 v = *reinterpret_cast<const float4*>(
        &g_h_src[(size_t)s * DIM + sub * 4]);
    float* o = out + (size_t)d * DIM + sub * 4;
    float a = v.x * w, b = v.y * w, c = v.z * w, e = v.w * w;
    asm volatile("red.global.add.v4.f32 [%0], {%1, %2, %3, %4};"
                 :: "l"(o), "f"(a), "f"(b), "f"(c), "f"(e)
                 : "memory");
}

extern "C" void kernel_launch(void* const* d_in, const int* in_sizes, int n_in,
                              void* d_out, int out_size)
{
    const float* x_src  = (const float*)d_in[0];
    const float* x_dst  = (const float*)d_in[1];
    const int*   eidx   = (const int*)d_in[2];   // [2, E] int32 (x64 disabled)
    const float* ew     = (const float*)d_in[3];
    const float* W_nei  = (const float*)d_in[4];
    const float* W_self = (const float*)d_in[5];
    const float* b_self = (const float*)d_in[6];
    float* out = (float*)d_out;

    int n_src = in_sizes[0] / DIM;
    int n_dst = in_sizes[1] / DIM;
    int E     = in_sizes[3];

    void* hsrc_ptr = nullptr;
    cudaGetSymbolAddress(&hsrc_ptr, g_h_src);

    // 1) self term (also initializes the poisoned output buffer)
    linear64_kernel<<<(n_dst + 255) / 256, 256>>>(x_dst, W_self, b_self, out, n_dst);
    // 2) neighbor transform into L2-resident scratch
    linear64_kernel<<<(n_src + 255) / 256, 256>>>(x_src, W_nei, nullptr,
                                                  (float*)hsrc_ptr, n_src);
    // 3) edge scatter with vectorized atomics
    long long threads = (long long)E * 16;
    int blocks = (int)((threads + 255) / 256);
    scatter_kernel<<<blocks, 256>>>(eidx, eidx + E, ew, out, E);
}